// round 10
// baseline (speedup 1.0000x reference)
#include <cuda_runtime.h>

// ThresholdEncode: out[i][2t]   = (x[i] <= th_t) && (x[i+1] >  th_t)
//                  out[i][2t+1] = (x[i] >  th_t) && (x[i+1] <= th_t)
// th_t = (t+1)/33, t in [0,32). Last row zeros. Output [n][64] fp32.
//
// At the DRAM-write floor (~6.85 TB/s). Final A/B: write-through stores
// (st.global.wt) instead of .cs — skips L2 dirty-line management on the
// write-once stream. Everything else identical to the bench-best config
// (one thread per float4, ITER=4, 256 tpb, exact-fit grid, hoisted
// thresholds, front-batched LDGs).

#define ITER 4

__device__ __forceinline__ void stwt4(float4* p, float4 v) {
    asm volatile("st.global.wt.v4.f32 [%0], {%1,%2,%3,%4};"
                 :: "l"(p), "f"(v.x), "f"(v.y), "f"(v.z), "f"(v.w)
                 : "memory");
}

__global__ void __launch_bounds__(256) ThresholdEncode_exact(
    const float* __restrict__ x, float4* __restrict__ out, int n) {

    const int stride  = gridDim.x * blockDim.x;   // multiple of 16
    const int i0      = blockIdx.x * blockDim.x + threadIdx.x;
    const int nm1     = n - 1;
    const int rowstep = stride >> 4;

    const int   q     = i0 & 15;                  // loop-invariant quadrant
    const float inv33 = 1.0f / 33.0f;
    const float th0   = (float)(2 * q + 1) * inv33;
    const float th1   = (float)(2 * q + 2) * inv33;

    const int row0 = i0 >> 4;

    // Front-batched loads: 8 independent LDGs in flight.
    float xp[ITER], xn[ITER];
    #pragma unroll
    for (int k = 0; k < ITER; k++) {
        int r = row0 + k * rowstep;
        xp[k] = __ldg(&x[r]);
        xn[k] = __ldg(&x[(r + 1 < n) ? (r + 1) : nm1]);  // clamp last row
    }

    #pragma unroll
    for (int k = 0; k < ITER; k++) {
        int r = row0 + k * rowstep;
        float4 v = make_float4(0.f, 0.f, 0.f, 0.f);
        if (r < nm1) {
            bool a0 = (xp[k] <= th0), b0 = (xn[k] > th0);
            bool a1 = (xp[k] <= th1), b1 = (xn[k] > th1);
            v.x = (a0 & b0)   ? 1.0f : 0.0f;   // up(t0)
            v.y = (!a0 & !b0) ? 1.0f : 0.0f;   // down(t0)
            v.z = (a1 & b1)   ? 1.0f : 0.0f;   // up(t1)
            v.w = (!a1 & !b1) ? 1.0f : 0.0f;   // down(t1)
        }
        stwt4(&out[i0 + k * stride], v);       // STG.128 write-through
    }
}

// General fallback for shapes where total doesn't divide the chunk.
__global__ void __launch_bounds__(256) ThresholdEncode_general(
    const float* __restrict__ x, float4* __restrict__ out, int n) {

    const int total  = n << 4;
    const int stride = gridDim.x * blockDim.x;
    const int i0     = blockIdx.x * blockDim.x + threadIdx.x;
    const int nm1    = n - 1;

    const int   q     = i0 & 15;
    const float inv33 = 1.0f / 33.0f;
    const float th0   = (float)(2 * q + 1) * inv33;
    const float th1   = (float)(2 * q + 2) * inv33;
    const int rowstep = stride >> 4;

    for (int base = i0; base < total; base += ITER * stride) {
        const int row0 = base >> 4;
        #pragma unroll
        for (int k = 0; k < ITER; k++) {
            int c = base + k * stride;
            if (c < total) {
                int row = row0 + k * rowstep;
                float4 v = make_float4(0.f, 0.f, 0.f, 0.f);
                if (row < nm1) {
                    float xp = __ldg(&x[row]);
                    float xn = __ldg(&x[row + 1]);
                    bool a0 = (xp <= th0), b0 = (xn > th0);
                    bool a1 = (xp <= th1), b1 = (xn > th1);
                    v.x = (a0 & b0)   ? 1.0f : 0.0f;
                    v.y = (!a0 & !b0) ? 1.0f : 0.0f;
                    v.z = (a1 & b1)   ? 1.0f : 0.0f;
                    v.w = (!a1 & !b1) ? 1.0f : 0.0f;
                }
                __stcs(&out[c], v);
            }
        }
    }
}

extern "C" void kernel_launch(void* const* d_in, const int* in_sizes, int n_in,
                              void* d_out, int out_size) {
    const float* x = (const float*)d_in[0];
    float4* out = (float4*)d_out;
    int n = in_sizes[0];

    int total   = n * 16;                        // float4 count
    int threads = 256;
    int chunk   = threads * ITER;                // 1024

    if (total % chunk == 0) {
        ThresholdEncode_exact<<<total / chunk, threads>>>(x, out, n);
    } else {
        int blocks = (total + chunk - 1) / chunk;
        ThresholdEncode_general<<<blocks, threads>>>(x, out, n);
    }
}

// round 11
// speedup vs baseline: 1.0718x; 1.0718x over previous
#include <cuda_runtime.h>

// ThresholdEncode: out[i][2t]   = (x[i] <= th_t) && (x[i+1] >  th_t)
//                  out[i][2t+1] = (x[i] >  th_t) && (x[i+1] <= th_t)
// th_t = (t+1)/33, t in [0,32). Last row zeros. Output [n][64] fp32.
//
// FINAL (converged at the DRAM-write floor: 6.89 TB/s sustained, 86% of
// 8 TB/s mixed spec). Best measured config across 10 rounds: one thread per
// float4 (2 thresholds), ITER=4, 256 threads/block, exact-fit grid,
// loop-invariant hoisted thresholds, front-batched LDGs, STG.128.cs
// (evict-first streaming — .wt and v8 variants both measured slower).

#define ITER 4

__global__ void __launch_bounds__(256) ThresholdEncode_exact(
    const float* __restrict__ x, float4* __restrict__ out, int n) {

    const int stride  = gridDim.x * blockDim.x;   // multiple of 16
    const int i0      = blockIdx.x * blockDim.x + threadIdx.x;
    const int nm1     = n - 1;
    const int rowstep = stride >> 4;

    const int   q     = i0 & 15;                  // loop-invariant quadrant
    const float inv33 = 1.0f / 33.0f;
    const float th0   = (float)(2 * q + 1) * inv33;
    const float th1   = (float)(2 * q + 2) * inv33;

    const int row0 = i0 >> 4;

    // Front-batched loads: 8 independent LDGs in flight.
    float xp[ITER], xn[ITER];
    #pragma unroll
    for (int k = 0; k < ITER; k++) {
        int r = row0 + k * rowstep;
        xp[k] = __ldg(&x[r]);
        xn[k] = __ldg(&x[(r + 1 < n) ? (r + 1) : nm1]);  // clamp last row
    }

    #pragma unroll
    for (int k = 0; k < ITER; k++) {
        int r = row0 + k * rowstep;
        float4 v = make_float4(0.f, 0.f, 0.f, 0.f);
        if (r < nm1) {
            bool a0 = (xp[k] <= th0), b0 = (xn[k] > th0);
            bool a1 = (xp[k] <= th1), b1 = (xn[k] > th1);
            v.x = (a0 & b0)   ? 1.0f : 0.0f;   // up(t0)
            v.y = (!a0 & !b0) ? 1.0f : 0.0f;   // down(t0)
            v.z = (a1 & b1)   ? 1.0f : 0.0f;   // up(t1)
            v.w = (!a1 & !b1) ? 1.0f : 0.0f;   // down(t1)
        }
        __stcs(&out[i0 + k * stride], v);      // STG.128, evict-first
    }
}

// General fallback for shapes where total doesn't divide the chunk.
__global__ void __launch_bounds__(256) ThresholdEncode_general(
    const float* __restrict__ x, float4* __restrict__ out, int n) {

    const int total  = n << 4;
    const int stride = gridDim.x * blockDim.x;
    const int i0     = blockIdx.x * blockDim.x + threadIdx.x;
    const int nm1    = n - 1;

    const int   q     = i0 & 15;
    const float inv33 = 1.0f / 33.0f;
    const float th0   = (float)(2 * q + 1) * inv33;
    const float th1   = (float)(2 * q + 2) * inv33;
    const int rowstep = stride >> 4;

    for (int base = i0; base < total; base += ITER * stride) {
        const int row0 = base >> 4;
        #pragma unroll
        for (int k = 0; k < ITER; k++) {
            int c = base + k * stride;
            if (c < total) {
                int row = row0 + k * rowstep;
                float4 v = make_float4(0.f, 0.f, 0.f, 0.f);
                if (row < nm1) {
                    float xp = __ldg(&x[row]);
                    float xn = __ldg(&x[row + 1]);
                    bool a0 = (xp <= th0), b0 = (xn > th0);
                    bool a1 = (xp <= th1), b1 = (xn > th1);
                    v.x = (a0 & b0)   ? 1.0f : 0.0f;
                    v.y = (!a0 & !b0) ? 1.0f : 0.0f;
                    v.z = (a1 & b1)   ? 1.0f : 0.0f;
                    v.w = (!a1 & !b1) ? 1.0f : 0.0f;
                }
                __stcs(&out[c], v);
            }
        }
    }
}

extern "C" void kernel_launch(void* const* d_in, const int* in_sizes, int n_in,
                              void* d_out, int out_size) {
    const float* x = (const float*)d_in[0];
    float4* out = (float4*)d_out;
    int n = in_sizes[0];

    int total   = n * 16;                        // float4 count
    int threads = 256;
    int chunk   = threads * ITER;                // 1024

    if (total % chunk == 0) {
        ThresholdEncode_exact<<<total / chunk, threads>>>(x, out, n);
    } else {
        int blocks = (total + chunk - 1) / chunk;
        ThresholdEncode_general<<<blocks, threads>>>(x, out, n);
    }
}

// round 12
// speedup vs baseline: 1.0911x; 1.0181x over previous
#include <cuda_runtime.h>

// ThresholdEncode: out[i][2t]   = (x[i] <= th_t) && (x[i+1] >  th_t)
//                  out[i][2t+1] = (x[i] >  th_t) && (x[i+1] <= th_t)
// th_t = (t+1)/33, t in [0,32). Last row zeros. Output [n][64] fp32.
//
// At the DRAM-write floor (~6.9 TB/s sustained). Last unsampled point in the
// batch-depth curve: ITER=2 float4 exact-fit (31250 blocks) — shallower
// store batch, shorter CTA lifetime, less cross-CTA L1tex-queue contention.
// Everything else identical to the record config (STG.128.cs, hoisted
// thresholds, front-batched LDGs, 256 tpb).

#define ITER 2

__global__ void __launch_bounds__(256) ThresholdEncode_exact(
    const float* __restrict__ x, float4* __restrict__ out, int n) {

    const int stride  = gridDim.x * blockDim.x;   // multiple of 16
    const int i0      = blockIdx.x * blockDim.x + threadIdx.x;
    const int nm1     = n - 1;
    const int rowstep = stride >> 4;

    const int   q     = i0 & 15;                  // loop-invariant quadrant
    const float inv33 = 1.0f / 33.0f;
    const float th0   = (float)(2 * q + 1) * inv33;
    const float th1   = (float)(2 * q + 2) * inv33;

    const int row0 = i0 >> 4;

    // Front-batched loads: 4 independent LDGs in flight.
    float xp[ITER], xn[ITER];
    #pragma unroll
    for (int k = 0; k < ITER; k++) {
        int r = row0 + k * rowstep;
        xp[k] = __ldg(&x[r]);
        xn[k] = __ldg(&x[(r + 1 < n) ? (r + 1) : nm1]);  // clamp last row
    }

    #pragma unroll
    for (int k = 0; k < ITER; k++) {
        int r = row0 + k * rowstep;
        float4 v = make_float4(0.f, 0.f, 0.f, 0.f);
        if (r < nm1) {
            bool a0 = (xp[k] <= th0), b0 = (xn[k] > th0);
            bool a1 = (xp[k] <= th1), b1 = (xn[k] > th1);
            v.x = (a0 & b0)   ? 1.0f : 0.0f;   // up(t0)
            v.y = (!a0 & !b0) ? 1.0f : 0.0f;   // down(t0)
            v.z = (a1 & b1)   ? 1.0f : 0.0f;   // up(t1)
            v.w = (!a1 & !b1) ? 1.0f : 0.0f;   // down(t1)
        }
        __stcs(&out[i0 + k * stride], v);      // STG.128, evict-first
    }
}

// General fallback for shapes where total doesn't divide the chunk.
__global__ void __launch_bounds__(256) ThresholdEncode_general(
    const float* __restrict__ x, float4* __restrict__ out, int n) {

    const int total  = n << 4;
    const int stride = gridDim.x * blockDim.x;
    const int i0     = blockIdx.x * blockDim.x + threadIdx.x;
    const int nm1    = n - 1;

    const int   q     = i0 & 15;
    const float inv33 = 1.0f / 33.0f;
    const float th0   = (float)(2 * q + 1) * inv33;
    const float th1   = (float)(2 * q + 2) * inv33;
    const int rowstep = stride >> 4;

    for (int base = i0; base < total; base += ITER * stride) {
        const int row0 = base >> 4;
        #pragma unroll
        for (int k = 0; k < ITER; k++) {
            int c = base + k * stride;
            if (c < total) {
                int row = row0 + k * rowstep;
                float4 v = make_float4(0.f, 0.f, 0.f, 0.f);
                if (row < nm1) {
                    float xp = __ldg(&x[row]);
                    float xn = __ldg(&x[row + 1]);
                    bool a0 = (xp <= th0), b0 = (xn > th0);
                    bool a1 = (xp <= th1), b1 = (xn > th1);
                    v.x = (a0 & b0)   ? 1.0f : 0.0f;
                    v.y = (!a0 & !b0) ? 1.0f : 0.0f;
                    v.z = (a1 & b1)   ? 1.0f : 0.0f;
                    v.w = (!a1 & !b1) ? 1.0f : 0.0f;
                }
                __stcs(&out[c], v);
            }
        }
    }
}

extern "C" void kernel_launch(void* const* d_in, const int* in_sizes, int n_in,
                              void* d_out, int out_size) {
    const float* x = (const float*)d_in[0];
    float4* out = (float4*)d_out;
    int n = in_sizes[0];

    int total   = n * 16;                        // float4 count
    int threads = 256;
    int chunk   = threads * ITER;                // 512

    if (total % chunk == 0) {
        ThresholdEncode_exact<<<total / chunk, threads>>>(x, out, n);
    } else {
        int blocks = (total + chunk - 1) / chunk;
        ThresholdEncode_general<<<blocks, threads>>>(x, out, n);
    }
}